// round 17
// baseline (speedup 1.0000x reference)
#include <cuda_runtime.h>
#include <math.h>
#include <stdint.h>

// Fixed shapes: x[131072,512] f32, clusters[64,512] f32, alpha scalar
#define DDIM 512
#define KDIM 64
#define TILE_ROWS 128
#define KC 32                    // k elements per chunk = 128 B per row (2 k-steps)
#define NCH (DDIM / KC)          // 16 chunks
#define THREADS 128              // 4 warps; warp w owns rows w*32..w*32+31
#define APITCH 144               // bytes per A row in smem (32 floats + 16 pad)
#define ASTAGE (TILE_ROWS * APITCH)  // 18432 B
#define NSTAGE 3

// SMEM layout (bytes): 3 A stages (reused as probs stage) + wred + flag
#define SM_A    0
#define SM_WRED (NSTAGE * ASTAGE)          // 55296
#define SMEM_TOTAL (SM_WRED + 32)          // 55328

#define MAXBLK 8192
__device__ uint2 g_bfh[32 * 256];          // bf16 B fragments [ks16][j*32+lane]
__device__ float g_partial[MAXBLK];        // per-block loss partials
__device__ unsigned int g_ticket = 0;      // completion ticket (self-resetting)

// ---- helpers ---------------------------------------------------------------
static __device__ __forceinline__ uint32_t smem_u32(const void* p) {
    uint32_t a;
    asm("{ .reg .u64 t; cvta.to.shared.u64 t, %1; cvt.u32.u64 %0, t; }"
        : "=r"(a) : "l"(p));
    return a;
}
static __device__ __forceinline__ void cp16(uint32_t saddr, const void* g) {
    asm volatile("cp.async.cg.shared.global [%0], [%1], 16;" :: "r"(saddr), "l"(g));
}
#define CP_COMMIT() asm volatile("cp.async.commit_group;" ::: "memory")
#define CP_WAIT2()  asm volatile("cp.async.wait_group 2;" ::: "memory")

// pack two f32 -> bf16x2 (round-to-nearest-even; low half = first arg)
static __device__ __forceinline__ uint32_t pack_bf16(float lo, float hi) {
    uint32_t r;
    asm("cvt.rn.bf16x2.f32 %0, %1, %2;" : "=r"(r) : "f"(hi), "f"(lo));
    return r;
}

static __device__ __forceinline__ void mma_bf16(float* c,
                                                uint32_t a0, uint32_t a1,
                                                uint32_t a2, uint32_t a3,
                                                uint32_t b0, uint32_t b1) {
    asm volatile(
        "mma.sync.aligned.m16n8k16.row.col.f32.bf16.bf16.f32 "
        "{%0,%1,%2,%3}, {%4,%5,%6,%7}, {%8,%9}, {%0,%1,%2,%3};"
        : "+f"(c[0]), "+f"(c[1]), "+f"(c[2]), "+f"(c[3])
        : "r"(a0), "r"(a1), "r"(a2), "r"(a3), "r"(b0), "r"(b1));
}

// ---------------------------------------------------------------------------
// Kernel 1: L2-normalize clusters, emit bf16 B fragments (m16n8k16 col-major).
// ---------------------------------------------------------------------------
__global__ void norm_clusters_kernel(const float* __restrict__ clusters) {
    int k = blockIdx.x;          // 64 blocks
    int t = threadIdx.x;         // 128 threads
    float4 v = ((const float4*)(clusters + (size_t)k * DDIM))[t];
    float ss = v.x * v.x + v.y * v.y + v.z * v.z + v.w * v.w;
    #pragma unroll
    for (int o = 16; o; o >>= 1) ss += __shfl_xor_sync(0xffffffffu, ss, o);
    __shared__ float ws[4];
    __shared__ float s_inv;
    __shared__ float sc[DDIM];
    if ((t & 31) == 0) ws[t >> 5] = ss;
    __syncthreads();
    if (t == 0) {
        float s = ws[0] + ws[1] + ws[2] + ws[3];
        s_inv = 1.0f / fmaxf(sqrtf(s), 1e-12f);
    }
    __syncthreads();
    float iv = s_inv;
    sc[t * 4 + 0] = v.x * iv;
    sc[t * 4 + 1] = v.y * iv;
    sc[t * 4 + 2] = v.z * iv;
    sc[t * 4 + 3] = v.w * iv;
    __syncthreads();
    {
        int ks = t >> 2, tg = t & 3;
        const float* s = sc + ks * 16 + tg * 2;
        uint2 b;
        b.x = pack_bf16(s[0], s[1]);
        b.y = pack_bf16(s[8], s[9]);
        g_bfh[ks * 256 + ((k >> 3) << 5) + ((k & 7) << 2) + tg] = b;
    }
}

// ---------------------------------------------------------------------------
// Kernel 2: bf16 m16n8k16 GEMM tile 128x64 + fused normalize/softmax/loss.
// Warp-private coalesced cp.async pipeline, 3 stages / distance-2.
// Probs staged in smem, streamed out with aligned float4 stores.
// Last CTA (atomic ticket) reduces the loss — no separate finalize kernel.
// ---------------------------------------------------------------------------
__global__ __launch_bounds__(THREADS, 4)
void cluster_mma_kernel(const float* __restrict__ x,
                        const float* __restrict__ alphap,
                        float* __restrict__ out,
                        int loss_off, int store_probs, int write_loss) {
    extern __shared__ char smem[];
    const uint32_t sb = smem_u32(smem);
    const int t = threadIdx.x;
    const int w = t >> 5, lane = t & 31;
    const int g = lane >> 2, tg = lane & 3;
    const size_t row0 = (size_t)blockIdx.x * TILE_ROWS;

    // Coalesced A loader: lane -> (arow = lane>>3, aseg = lane&7).
    // Instruction q: rows w*32 + q*4 + arow; 4 full 128B lines per instr.
    const int arow = lane >> 3, aseg = lane & 7;
    const float* xb = x + (row0 + w * 32 + arow) * DDIM + aseg * 4;
    const uint32_t sbA = sb + SM_A + (w * 32 + arow) * APITCH + aseg * 16;

    // ---- prologue: issue chunks 0 and 1 ----
    #pragma unroll
    for (int pc = 0; pc < 2; ++pc) {
        const float* src = xb + pc * KC;
        uint32_t ab = sbA + pc * ASTAGE;
        #pragma unroll
        for (int q = 0; q < 8; ++q)
            cp16(ab + q * 4 * APITCH, src + (size_t)q * 4 * DDIM);
        CP_COMMIT();
    }

    float acc[2][8][4];
    #pragma unroll
    for (int m = 0; m < 2; ++m)
        #pragma unroll
        for (int j = 0; j < 8; ++j)
            #pragma unroll
            for (int r = 0; r < 4; ++r) acc[m][j][r] = 0.f;
    float ssq[4] = {0.f, 0.f, 0.f, 0.f};

    // ---- mainloop: warp-private 3-stage, distance-2 pipeline ----
    int st = 0;                           // stage of chunk c (c % 3)
    for (int c = 0; c < NCH; ++c) {
        // B fragments for kstep 2c (prefetched ahead of the wait)
        uint2 b[8];
        {
            const uint2* bp = g_bfh + (2 * c) * 256 + lane;
            #pragma unroll
            for (int j = 0; j < 8; ++j) b[j] = __ldg(bp + j * 32);
        }

        if (c + 2 < NCH) {                // issue chunk c+2 into freed stage
            const float* src = xb + (c + 2) * KC;
            int st2 = st - 1 + ((st - 1 < 0) ? 3 : 0);   // (c+2) % 3
            uint32_t ab = sbA + st2 * ASTAGE;
            #pragma unroll
            for (int q = 0; q < 8; ++q)
                cp16(ab + q * 4 * APITCH, src + (size_t)q * 4 * DDIM);
        }
        CP_COMMIT();                      // always commit (empty near tail)
        CP_WAIT2();                       // chunk c complete; <=2 pending
        __syncwarp();

        const char* ap = smem + SM_A + st * ASTAGE;
        if (++st == NSTAGE) st = 0;

        #pragma unroll
        for (int u = 0; u < 2; ++u) {
            if (u == 1) {
                const uint2* bp = g_bfh + (2 * c + 1) * 256 + lane;
                #pragma unroll
                for (int j = 0; j < 8; ++j) b[j] = __ldg(bp + j * 32);
            }
            #pragma unroll
            for (int m = 0; m < 2; ++m) {
                const char* r0 = ap + (w * 32 + m * 16 + g) * APITCH + u * 64 + tg * 8;
                const char* r1 = r0 + 8 * APITCH;
                float2 v0 = *(const float2*)(r0);
                float2 v1 = *(const float2*)(r1);
                float2 v2 = *(const float2*)(r0 + 32);
                float2 v3 = *(const float2*)(r1 + 32);
                ssq[2 * m]     += v0.x * v0.x + v0.y * v0.y + v2.x * v2.x + v2.y * v2.y;
                ssq[2 * m + 1] += v1.x * v1.x + v1.y * v1.y + v3.x * v3.x + v3.y * v3.y;
                uint32_t a0 = pack_bf16(v0.x, v0.y);
                uint32_t a1 = pack_bf16(v1.x, v1.y);
                uint32_t a2 = pack_bf16(v2.x, v2.y);
                uint32_t a3 = pack_bf16(v3.x, v3.y);
                #pragma unroll
                for (int j = 0; j < 8; ++j)
                    mma_bf16(acc[m][j], a0, a1, a2, a3, b[j].x, b[j].y);
            }
        }
    }

    // ---- finalize norms: reduce over the 4 quad (tg) lanes ----
    #pragma unroll
    for (int i = 0; i < 4; ++i) {
        ssq[i] += __shfl_xor_sync(0xffffffffu, ssq[i], 1);
        ssq[i] += __shfl_xor_sync(0xffffffffu, ssq[i], 2);
    }

    const float alphav = *alphap;
    float lossacc = 0.f;

    // Probs stage aligned mod 16 to the global destination (+loss_off shift).
    float* gdst = out + (size_t)loss_off + row0 * KDIM;
    char* sstage = smem + SM_A + (int)((size_t)gdst & 12);

    if (store_probs) __syncthreads();   // all warps done reading A stages

    // ---- epilogue: per-row scale, softmax over 64 (quad-shfl), stage, loss ----
    #pragma unroll
    for (int i = 0; i < 4; ++i) {      // local row lrow = w*32 + i*8 + g
        const int m = i >> 1, hi = i & 1;
        float inv = 1.0f / fmaxf(sqrtf(ssq[i]), 1e-12f);
        float s[16];
        #pragma unroll
        for (int j = 0; j < 8; ++j) {
            s[2 * j]     = acc[m][j][hi * 2]     * inv;
            s[2 * j + 1] = acc[m][j][hi * 2 + 1] * inv;
        }
        float mx = -1e30f;
        #pragma unroll
        for (int j = 0; j < 16; ++j) mx = fmaxf(mx, s[j] * alphav);
        mx = fmaxf(mx, __shfl_xor_sync(0xffffffffu, mx, 1));
        mx = fmaxf(mx, __shfl_xor_sync(0xffffffffu, mx, 2));
        float e[16];
        float es = 0.f, ps = 0.f;
        #pragma unroll
        for (int j = 0; j < 16; ++j) {
            e[j] = __expf(s[j] * alphav - mx);
            es += e[j];
            ps += e[j] * s[j];
        }
        es += __shfl_xor_sync(0xffffffffu, es, 1);
        es += __shfl_xor_sync(0xffffffffu, es, 2);
        ps += __shfl_xor_sync(0xffffffffu, ps, 1);
        ps += __shfl_xor_sync(0xffffffffu, ps, 2);
        float rs = 1.0f / es;
        if (tg == 0) lossacc += ps * rs;
        if (store_probs) {
            int lrow = w * 32 + i * 8 + g;
            float* sb_row = (float*)(sstage) + lrow * KDIM + tg * 2;
            #pragma unroll
            for (int j = 0; j < 8; ++j) {
                sb_row[j * 8]     = e[2 * j] * rs;
                sb_row[j * 8 + 1] = e[2 * j + 1] * rs;
            }
        }
    }

    // ---- cooperative aligned copy-out of the staged probs tile ----
    if (store_probs) {
        __syncthreads();                // stage complete
        const int total_f = TILE_ROWS * KDIM;                 // 8192 floats
        const int head_f = (int)(((16 - ((size_t)gdst & 15)) & 15) >> 2);
        for (int i = t; i < head_f; i += THREADS)
            gdst[i] = *(const float*)(sstage + (size_t)i * 4);
        const int nf4 = (total_f - head_f) >> 2;
        const float4* s4 = (const float4*)(sstage + (size_t)head_f * 4);
        float4* g4 = (float4*)(gdst + head_f);
        for (int q = t; q < nf4; q += THREADS) g4[q] = s4[q];
        const int done = head_f + nf4 * 4;
        for (int i = done + t; i < total_f; i += THREADS)
            gdst[i] = *(const float*)(sstage + (size_t)i * 4);
    }

    // ---- deterministic per-block loss partial ----
    #pragma unroll
    for (int o = 16; o; o >>= 1) lossacc += __shfl_xor_sync(0xffffffffu, lossacc, o);
    float* wred = (float*)(smem + SM_WRED);
    unsigned int* flag = (unsigned int*)(smem + SM_WRED + 16);
    if (lane == 0) wred[w] = lossacc;
    __syncthreads();
    if (t == 0) {
        g_partial[blockIdx.x] = wred[0] + wred[1] + wred[2] + wred[3];
        __threadfence();
        unsigned int tk = atomicAdd(&g_ticket, 1u);
        *flag = (tk == (unsigned int)(gridDim.x - 1)) ? 1u : 0u;
    }
    __syncthreads();

    // ---- last CTA: deterministic loss reduction (fixed index order) ----
    if (*flag) {
        int nblocks = gridDim.x;
        float s = 0.f;
        for (int i = t; i < nblocks; i += THREADS) s += g_partial[i];
        #pragma unroll
        for (int o = 16; o; o >>= 1) s += __shfl_xor_sync(0xffffffffu, s, o);
        if (lane == 0) wred[w] = s;
        __syncthreads();
        if (t == 0) {
            float tot = wred[0] + wred[1] + wred[2] + wred[3];
            if (write_loss)
                out[0] = -tot / (float)((size_t)nblocks * TILE_ROWS);
            atomicExch(&g_ticket, 0u);      // reset for next graph replay
        }
    }
}

// ---------------------------------------------------------------------------
extern "C" void kernel_launch(void* const* d_in, const int* in_sizes, int n_in,
                              void* d_out, int out_size) {
    const float* x        = (const float*)d_in[0];
    const float* clusters = (const float*)d_in[1];
    const float* alpha    = (const float*)d_in[2];
    float* out = (float*)d_out;

    int N = in_sizes[0] / DDIM;              // 131072
    int nblocks = N / TILE_ROWS;             // 1024

    // Output layout (confirmed): out[0]=loss, out[1:]=probs when size nk+1
    long long nk = (long long)N * KDIM;
    int loss_off = 0, store_probs = 1, write_loss = 0;
    if ((long long)out_size == nk + 1) { loss_off = 1; write_loss = 1; }
    else if ((long long)out_size == nk) { loss_off = 0; write_loss = 0; }
    else { store_probs = 0; write_loss = 1; }

    cudaFuncSetAttribute(cluster_mma_kernel,
                         cudaFuncAttributeMaxDynamicSharedMemorySize, SMEM_TOTAL);

    norm_clusters_kernel<<<KDIM, 128>>>(clusters);
    cluster_mma_kernel<<<nblocks, THREADS, SMEM_TOTAL>>>(x, alpha, out,
                                                         loss_off, store_probs,
                                                         write_loss);
}